// round 5
// baseline (speedup 1.0000x reference)
#include <cuda_runtime.h>
#include <math.h>

// Problem constants
#define B_  4
#define T_  2048
#define D_  512
#define H_  8
#define DK_ 64
#define BT_ (B_ * T_)

// ---------------- device scratch (no allocations allowed) ----------------
__device__ float g_sq[T_], g_sk[T_], g_sv[T_], g_sx[T_];       // per-token act scales
__device__ float g_wsq[D_], g_wsk[D_], g_wsv[D_];              // per-col weight scales
__device__ signed char g_aq[BT_ * D_], g_ak[BT_ * D_], g_av[BT_ * D_]; // int8 acts
__device__ signed char g_xq8[BT_ * D_];                         // int8 of attention out
__device__ signed char g_wtq[D_ * D_], g_wtk[D_ * D_], g_wtv[D_ * D_]; // int8 W^T [j][k]
__device__ float g_q[B_ * H_ * T_ * DK_];
__device__ float g_kk[B_ * H_ * T_ * DK_];
__device__ float g_vv[B_ * H_ * T_ * DK_];
__device__ float g_x[BT_ * D_];

// ---- emulate XLA:GPU's f32 division (div.full.f32, <=2ulp, not IEEE) ----
__device__ __forceinline__ float div_full(float a, float b) {
    float r;
    asm("div.full.f32 %0, %1, %2;" : "=f"(r) : "f"(a), "f"(b));
    return r;
}
__device__ __forceinline__ float make_scale(float absmax) {
    return fmaxf(div_full(absmax, 127.0f), 1e-8f);
}
__device__ __forceinline__ signed char quant_val(float v, float s) {
    float q = rintf(div_full(v, s));
    q = fminf(127.0f, fmaxf(-128.0f, q));
    return (signed char)(int)q;
}

// ---------------- per-token activation scale + int8 quantize ------------------
// grid (T_, 3) for q/k/v, or grid (T_,1) final_mode=1 for g_x -> g_xq8.
__global__ void act_quant_kernel(const float* __restrict__ xq,
                                 const float* __restrict__ xk,
                                 const float* __restrict__ xv,
                                 int final_mode) {
    int t = blockIdx.x;
    const float* x;
    float* sptr;
    signed char* outq;
    if (final_mode) {
        x = g_x; sptr = g_sx; outq = g_xq8;
    } else {
        int sel = blockIdx.y;
        x = (sel == 0) ? xq : (sel == 1) ? xk : xv;
        sptr = (sel == 0) ? g_sq : (sel == 1) ? g_sk : g_sv;
        outq = (sel == 0) ? g_aq : (sel == 1) ? g_ak : g_av;
    }
    int tid = threadIdx.x;
    float m = 0.0f;
    for (int idx = tid; idx < B_ * D_; idx += 256) {
        int b = idx >> 9;          // D_ = 512
        int d = idx & (D_ - 1);
        m = fmaxf(m, fabsf(x[(b * T_ + t) * D_ + d]));
    }
    __shared__ float red[256];
    __shared__ float s_sh;
    red[tid] = m;
    __syncthreads();
    for (int s2 = 128; s2 > 0; s2 >>= 1) {
        if (tid < s2) red[tid] = fmaxf(red[tid], red[tid + s2]);
        __syncthreads();
    }
    if (tid == 0) { s_sh = make_scale(red[0]); sptr[t] = s_sh; }
    __syncthreads();
    float s = s_sh;
    for (int idx = tid; idx < B_ * D_; idx += 256) {
        int b = idx >> 9;
        int d = idx & (D_ - 1);
        int off = (b * T_ + t) * D_ + d;
        outq[off] = quant_val(x[off], s);
    }
}

// ---------------- weight quant: per-col scale, store int8 W^T -----------------
// grid (D_/64, 3), 256 threads.
__global__ void weight_quant_kernel(const float* __restrict__ Wq,
                                    const float* __restrict__ Wk,
                                    const float* __restrict__ Wv) {
    int sel = blockIdx.y;
    const float* W = (sel == 0) ? Wq : (sel == 1) ? Wk : Wv;
    signed char* WT = (sel == 0) ? g_wtq : (sel == 1) ? g_wtk : g_wtv;
    float* WS = (sel == 0) ? g_wsq : (sel == 1) ? g_wsk : g_wsv;

    int j0 = blockIdx.x * 64;
    int tid = threadIdx.x;
    int tx = tid & 63;
    int ty = tid >> 6;  // 0..3

    float m = 0.0f;
    for (int i = ty; i < D_; i += 4)
        m = fmaxf(m, fabsf(W[i * D_ + j0 + tx]));

    __shared__ float red[4][64];
    __shared__ float sc[64];
    __shared__ signed char tile[64][68];  // [j][m] transposed stage
    red[ty][tx] = m;
    __syncthreads();
    if (ty == 0) {
        float mm = fmaxf(fmaxf(red[0][tx], red[1][tx]), fmaxf(red[2][tx], red[3][tx]));
        sc[tx] = make_scale(mm);
        WS[j0 + tx] = sc[tx];
    }
    __syncthreads();

    for (int kb = 0; kb < D_ / 64; kb++) {
        for (int u = 0; u < 16; u++) {
            int idx = tid + u * 256;
            int mrow = idx >> 6;
            int j = idx & 63;
            float w = W[(kb * 64 + mrow) * D_ + j0 + j];
            tile[j][mrow] = quant_val(w, sc[j]);
        }
        __syncthreads();
        int j = tid >> 2;
        for (int u = 0; u < 4; u++) {
            int mw = (tid & 3) + u * 4;
            unsigned int v = ((unsigned char)tile[j][mw * 4 + 0]) |
                             ((unsigned int)(unsigned char)tile[j][mw * 4 + 1] << 8) |
                             ((unsigned int)(unsigned char)tile[j][mw * 4 + 2] << 16) |
                             ((unsigned int)(unsigned char)tile[j][mw * 4 + 3] << 24);
            ((unsigned int*)WT)[(j0 + j) * (D_ / 4) + kb * 16 + mw] = v;
        }
        __syncthreads();
    }
}

// ---------------- projection GEMM: int8 dp4a, exact int32 accumulate ----------
// grid (D_/64, BT_/64, 3), 256 threads. Output in head layout fp32.
__global__ void proj_gemm_i8_kernel() {
    int z = blockIdx.z;
    const signed char* A = (z == 0) ? g_aq : (z == 1) ? g_ak : g_av;
    const signed char* WT = (z == 0) ? g_wtq : (z == 1) ? g_wtk : g_wtv;
    const float* sA = (z == 0) ? g_sq : (z == 1) ? g_sk : g_sv;
    const float* sW = (z == 0) ? g_wsq : (z == 1) ? g_wsk : g_wsv;
    float* OUT = (z == 0) ? g_q : (z == 1) ? g_kk : g_vv;

    int row0 = blockIdx.y * 64;
    int col0 = blockIdx.x * 64;
    int tid = threadIdx.x;
    int tx = tid & 15;
    int ty = tid >> 4;

    __shared__ int As[64 * 17];
    __shared__ int Bs[64 * 17];

    int acc[4][4];
#pragma unroll
    for (int i = 0; i < 4; i++)
#pragma unroll
        for (int j = 0; j < 4; j++) acc[i][j] = 0;

    const int* Ai = (const int*)A;
    const int* Bi = (const int*)WT;
    int m = tid >> 2;
    int g = tid & 3;

    for (int kb = 0; kb < D_ / 64; kb++) {
        int4 av = *(const int4*)(&Ai[(row0 + m) * (D_ / 4) + kb * 16 + g * 4]);
        int4 bv = *(const int4*)(&Bi[(col0 + m) * (D_ / 4) + kb * 16 + g * 4]);
        As[m * 17 + g * 4 + 0] = av.x;
        As[m * 17 + g * 4 + 1] = av.y;
        As[m * 17 + g * 4 + 2] = av.z;
        As[m * 17 + g * 4 + 3] = av.w;
        Bs[m * 17 + g * 4 + 0] = bv.x;
        Bs[m * 17 + g * 4 + 1] = bv.y;
        Bs[m * 17 + g * 4 + 2] = bv.z;
        Bs[m * 17 + g * 4 + 3] = bv.w;
        __syncthreads();
#pragma unroll
        for (int kk = 0; kk < 16; kk++) {
            int a4[4], b4[4];
#pragma unroll
            for (int i = 0; i < 4; i++) a4[i] = As[(ty * 4 + i) * 17 + kk];
#pragma unroll
            for (int j = 0; j < 4; j++) b4[j] = Bs[(tx * 4 + j) * 17 + kk];
#pragma unroll
            for (int i = 0; i < 4; i++)
#pragma unroll
                for (int j = 0; j < 4; j++) acc[i][j] = __dp4a(a4[i], b4[j], acc[i][j]);
        }
        __syncthreads();
    }

    int h = col0 >> 6;  // 64-col tile == one head
#pragma unroll
    for (int i = 0; i < 4; i++) {
        int r = row0 + ty * 4 + i;
        int b = r >> 11;          // T_ = 2048
        int t = r & (T_ - 1);
        float st = sA[t];
        float4 v;
        v.x = (float)acc[i][0] * (st * sW[col0 + tx * 4 + 0]);
        v.y = (float)acc[i][1] * (st * sW[col0 + tx * 4 + 1]);
        v.z = (float)acc[i][2] * (st * sW[col0 + tx * 4 + 2]);
        v.w = (float)acc[i][3] * (st * sW[col0 + tx * 4 + 3]);
        *(float4*)(&OUT[((b * H_ + h) * T_ + t) * DK_ + tx * 4]) = v;
    }
}

// ---------------- final GEMM: dequant(int8 x) @ Wf (fp32) -> d_out ------------
__global__ void final_gemm_kernel(const float* __restrict__ Wf,
                                  float* __restrict__ out) {
    int row0 = blockIdx.y * 64;
    int col0 = blockIdx.x * 64;
    int tid = threadIdx.x;
    int tx = tid & 15;
    int ty = tid >> 4;

    __shared__ float As[16][68];
    __shared__ float Bs[16][64];

    float acc[4][4];
#pragma unroll
    for (int i = 0; i < 4; i++)
#pragma unroll
        for (int j = 0; j < 4; j++) acc[i][j] = 0.0f;

    int m = tid >> 2;
    int g = tid & 3;
    float sm_scale = g_sx[(row0 + m) & (T_ - 1)];

    for (int kb = 0; kb < D_ / 16; kb++) {
        int av = ((const int*)g_xq8)[(row0 + m) * (D_ / 4) + kb * 4 + g];
#pragma unroll
        for (int u = 0; u < 4; u++) {
            int q8 = (av << (24 - 8 * u)) >> 24;  // sign-extended byte u
            As[g * 4 + u][m] = (float)q8 * sm_scale;
        }
#pragma unroll
        for (int i = 0; i < 4; i++) {
            int idx = tid + i * 256;
            int k = idx >> 6;
            int n = idx & 63;
            Bs[k][n] = Wf[(kb * 16 + k) * D_ + col0 + n];
        }
        __syncthreads();
#pragma unroll
        for (int k = 0; k < 16; k++) {
            float4 a = *(const float4*)(&As[k][ty * 4]);
            float4 b = *(const float4*)(&Bs[k][tx * 4]);
            float avv[4] = {a.x, a.y, a.z, a.w};
            float bvv[4] = {b.x, b.y, b.z, b.w};
#pragma unroll
            for (int i = 0; i < 4; i++)
#pragma unroll
                for (int j = 0; j < 4; j++) acc[i][j] += avv[i] * bvv[j];
        }
        __syncthreads();
    }

#pragma unroll
    for (int i = 0; i < 4; i++) {
        int r = row0 + ty * 4 + i;
        float4 v = make_float4(acc[i][0], acc[i][1], acc[i][2], acc[i][3]);
        *(float4*)(&out[r * D_ + col0 + tx * 4]) = v;
    }
}

// ---------------- attention: two-pass softmax, fp32, div.full semantics -------
// Pass A: row max m, l = sum exp(s-m).  Pass B: p = div_full(exp(s-m), l), PV.
// grid (T_/64, B_*H_), 256 threads.
#define ATT_SMEM ((64 * 64 + 64 * 68 + 64 * 64) * 4)

__global__ void attention_kernel() {
    extern __shared__ float sm[];
    float* Qs = sm;                      // stride 64
    float* Ks = sm + 64 * 64;            // stride 68 ; aliased as Ps in pass B
    float* Vs = sm + 64 * 64 + 64 * 68;  // stride 64

    int bh = blockIdx.y;
    int q0 = blockIdx.x * 64;
    const float* Q = g_q + bh * T_ * DK_;
    const float* K = g_kk + bh * T_ * DK_;
    const float* V = g_vv + bh * T_ * DK_;

    int tid = threadIdx.x;
    int tx = tid & 15;
    int ty = tid >> 4;

    for (int idx = tid; idx < 64 * 64; idx += 256) {
        int m = idx >> 6;
        int d = idx & 63;
        Qs[m * 64 + d] = Q[(q0 + m) * DK_ + d];
    }

    float mrow[4], lrow[4];
#pragma unroll
    for (int i = 0; i < 4; i++) { mrow[i] = -1e30f; lrow[i] = 0.0f; }

    // ---------------- pass A: m and l ----------------
    for (int kt = 0; kt < T_ / 64; kt++) {
        __syncthreads();
        for (int idx = tid; idx < 64 * 64; idx += 256) {
            int j = idx >> 6;
            int d = idx & 63;
            Ks[j * 68 + d] = K[(kt * 64 + j) * DK_ + d];
        }
        __syncthreads();

        float s_[4][4];
#pragma unroll
        for (int i = 0; i < 4; i++)
#pragma unroll
            for (int j = 0; j < 4; j++) s_[i][j] = 0.0f;

        for (int d = 0; d < 64; d += 4) {
            float4 qv[4], kv[4];
#pragma unroll
            for (int i = 0; i < 4; i++)
                qv[i] = *(const float4*)(&Qs[(ty * 4 + i) * 64 + d]);
#pragma unroll
            for (int j = 0; j < 4; j++)
                kv[j] = *(const float4*)(&Ks[(tx * 4 + j) * 68 + d]);
#pragma unroll
            for (int i = 0; i < 4; i++)
#pragma unroll
                for (int j = 0; j < 4; j++) {
                    s_[i][j] += qv[i].x * kv[j].x;
                    s_[i][j] += qv[i].y * kv[j].y;
                    s_[i][j] += qv[i].z * kv[j].z;
                    s_[i][j] += qv[i].w * kv[j].w;
                }
        }

#pragma unroll
        for (int i = 0; i < 4; i++) {
            float tm = -1e30f;
#pragma unroll
            for (int j = 0; j < 4; j++) {
                s_[i][j] = div_full(s_[i][j], 8.0f);   // scores / sqrt(dk)
                tm = fmaxf(tm, s_[i][j]);
            }
#pragma unroll
            for (int off = 8; off > 0; off >>= 1)
                tm = fmaxf(tm, __shfl_xor_sync(0xFFFFFFFFu, tm, off, 16));
            float newm = fmaxf(mrow[i], tm);
            float alpha = expf(mrow[i] - newm);
            float rs = 0.0f;
#pragma unroll
            for (int j = 0; j < 4; j++) rs += expf(s_[i][j] - newm);
#pragma unroll
            for (int off = 8; off > 0; off >>= 1)
                rs += __shfl_xor_sync(0xFFFFFFFFu, rs, off, 16);
            lrow[i] = lrow[i] * alpha + rs;
            mrow[i] = newm;
        }
    }

    // ---------------- pass B: p = div_full(exp(s-m), l), O = p @ V -------------
    float Ov[4][4];
#pragma unroll
    for (int i = 0; i < 4; i++)
#pragma unroll
        for (int j = 0; j < 4; j++) Ov[i][j] = 0.0f;

    for (int kt = 0; kt < T_ / 64; kt++) {
        __syncthreads();
        for (int idx = tid; idx < 64 * 64; idx += 256) {
            int j = idx >> 6;
            int d = idx & 63;
            Ks[j * 68 + d] = K[(kt * 64 + j) * DK_ + d];
            Vs[j * 64 + d] = V[(kt * 64 + j) * DK_ + d];
        }
        __syncthreads();

        float s_[4][4];
#pragma unroll
        for (int i = 0; i < 4; i++)
#pragma unroll
            for (int j = 0; j < 4; j++) s_[i][j] = 0.0f;

        for (int d = 0; d < 64; d += 4) {
            float4 qv[4], kv[4];
#pragma unroll
            for (int i = 0; i < 4; i++)
                qv[i] = *(const float4*)(&Qs[(ty * 4 + i) * 64 + d]);
#pragma unroll
            for (int j = 0; j < 4; j++)
                kv[j] = *(const float4*)(&Ks[(tx * 4 + j) * 68 + d]);
#pragma unroll
            for (int i = 0; i < 4; i++)
#pragma unroll
                for (int j = 0; j < 4; j++) {
                    s_[i][j] += qv[i].x * kv[j].x;
                    s_[i][j] += qv[i].y * kv[j].y;
                    s_[i][j] += qv[i].z * kv[j].z;
                    s_[i][j] += qv[i].w * kv[j].w;
                }
        }
        __syncthreads();  // Ks reads done; safe to overwrite with Ps

#pragma unroll
        for (int i = 0; i < 4; i++) {
            float p[4];
#pragma unroll
            for (int j = 0; j < 4; j++) {
                float sv = div_full(s_[i][j], 8.0f);
                p[j] = div_full(expf(sv - mrow[i]), lrow[i]);
            }
            *(float4*)(&Ks[(ty * 4 + i) * 68 + tx * 4]) =
                make_float4(p[0], p[1], p[2], p[3]);
        }
        __syncthreads();

        for (int j = 0; j < 64; j += 4) {
            float4 pv[4], vr[4];
#pragma unroll
            for (int i = 0; i < 4; i++)
                pv[i] = *(const float4*)(&Ks[(ty * 4 + i) * 68 + j]);
#pragma unroll
            for (int jj = 0; jj < 4; jj++)
                vr[jj] = *(const float4*)(&Vs[(j + jj) * 64 + tx * 4]);
#pragma unroll
            for (int i = 0; i < 4; i++) {
                float pw[4] = {pv[i].x, pv[i].y, pv[i].z, pv[i].w};
#pragma unroll
                for (int jj = 0; jj < 4; jj++) {
                    Ov[i][0] += pw[jj] * vr[jj].x;
                    Ov[i][1] += pw[jj] * vr[jj].y;
                    Ov[i][2] += pw[jj] * vr[jj].z;
                    Ov[i][3] += pw[jj] * vr[jj].w;
                }
            }
        }
    }

    int b = bh >> 3;   // H_ = 8
    int h = bh & 7;
#pragma unroll
    for (int i = 0; i < 4; i++) {
        int t = q0 + ty * 4 + i;
        float4 v = make_float4(Ov[i][0], Ov[i][1], Ov[i][2], Ov[i][3]);
        *(float4*)(&g_x[(b * T_ + t) * D_ + h * DK_ + tx * 4]) = v;
    }
}

// ------------------------------ launcher --------------------------------------
extern "C" void kernel_launch(void* const* d_in, const int* in_sizes, int n_in,
                              void* d_out, int out_size) {
    (void)in_sizes; (void)n_in; (void)out_size;
    const float* q  = (const float*)d_in[0];
    const float* k  = (const float*)d_in[1];
    const float* v  = (const float*)d_in[2];
    const float* Wq = (const float*)d_in[3];
    const float* Wk = (const float*)d_in[4];
    const float* Wv = (const float*)d_in[5];
    const float* Wf = (const float*)d_in[6];
    float* out = (float*)d_out;

    cudaFuncSetAttribute(attention_kernel,
                         cudaFuncAttributeMaxDynamicSharedMemorySize, ATT_SMEM);

    act_quant_kernel<<<dim3(T_, 3), 256>>>(q, k, v, 0);
    weight_quant_kernel<<<dim3(D_ / 64, 3), 256>>>(Wq, Wk, Wv);
    proj_gemm_i8_kernel<<<dim3(D_ / 64, BT_ / 64, 3), 256>>>();
    attention_kernel<<<dim3(T_ / 64, B_ * H_), 256, ATT_SMEM>>>();
    act_quant_kernel<<<dim3(T_, 1), 256>>>(q, k, v, 1);
    final_gemm_kernel<<<dim3(D_ / 64, BT_ / 64), 256>>>(Wf, out);
}

// round 6
// speedup vs baseline: 2.2550x; 2.2550x over previous
#include <cuda_runtime.h>
#include <math.h>

// Problem constants
#define B_  4
#define T_  2048
#define D_  512
#define H_  8
#define DK_ 64
#define BT_ (B_ * T_)

// ---------------- device scratch (no allocations allowed) ----------------
__device__ float g_sq[T_], g_sk[T_], g_sv[T_], g_sx[T_];       // per-token act scales
__device__ float g_wsq[D_], g_wsk[D_], g_wsv[D_];              // per-col weight scales
__device__ signed char g_aq[BT_ * D_], g_ak[BT_ * D_], g_av[BT_ * D_]; // int8 acts
__device__ signed char g_xq8[BT_ * D_];                         // int8 of attention out
__device__ signed char g_wtq[D_ * D_], g_wtk[D_ * D_], g_wtv[D_ * D_]; // int8 W^T [j][k]
__device__ float g_q[B_ * H_ * T_ * DK_];
__device__ float g_kk[B_ * H_ * T_ * DK_];
__device__ float g_vv[B_ * H_ * T_ * DK_];
__device__ float g_x[BT_ * D_];

// ---- emulate XLA:GPU's f32 division (div.full.f32, <=2ulp, not IEEE) ----
__device__ __forceinline__ float div_full(float a, float b) {
    float r;
    asm("div.full.f32 %0, %1, %2;" : "=f"(r) : "f"(a), "f"(b));
    return r;
}
__device__ __forceinline__ float make_scale(float absmax) {
    return fmaxf(div_full(absmax, 127.0f), 1e-8f);
}
__device__ __forceinline__ signed char quant_val(float v, float s) {
    float q = rintf(div_full(v, s));
    q = fminf(127.0f, fmaxf(-128.0f, q));
    return (signed char)(int)q;
}

// ---------------- per-token activation scale + int8 quantize ------------------
// grid (T_, 3) for q/k/v, or grid (T_,1) final_mode=1 for g_x -> g_xq8.
__global__ void act_quant_kernel(const float* __restrict__ xq,
                                 const float* __restrict__ xk,
                                 const float* __restrict__ xv,
                                 int final_mode) {
    int t = blockIdx.x;
    const float* x;
    float* sptr;
    signed char* outq;
    if (final_mode) {
        x = g_x; sptr = g_sx; outq = g_xq8;
    } else {
        int sel = blockIdx.y;
        x = (sel == 0) ? xq : (sel == 1) ? xk : xv;
        sptr = (sel == 0) ? g_sq : (sel == 1) ? g_sk : g_sv;
        outq = (sel == 0) ? g_aq : (sel == 1) ? g_ak : g_av;
    }
    int tid = threadIdx.x;
    float m = 0.0f;
    for (int idx = tid; idx < B_ * D_; idx += 256) {
        int b = idx >> 9;          // D_ = 512
        int d = idx & (D_ - 1);
        m = fmaxf(m, fabsf(x[(b * T_ + t) * D_ + d]));
    }
    __shared__ float red[256];
    __shared__ float s_sh;
    red[tid] = m;
    __syncthreads();
    for (int s2 = 128; s2 > 0; s2 >>= 1) {
        if (tid < s2) red[tid] = fmaxf(red[tid], red[tid + s2]);
        __syncthreads();
    }
    if (tid == 0) { s_sh = make_scale(red[0]); sptr[t] = s_sh; }
    __syncthreads();
    float s = s_sh;
    for (int idx = tid; idx < B_ * D_; idx += 256) {
        int b = idx >> 9;
        int d = idx & (D_ - 1);
        int off = (b * T_ + t) * D_ + d;
        outq[off] = quant_val(x[off], s);
    }
}

// ---------------- weight quant: per-col scale, store int8 W^T -----------------
// grid (D_/64, 3), 256 threads.
__global__ void weight_quant_kernel(const float* __restrict__ Wq,
                                    const float* __restrict__ Wk,
                                    const float* __restrict__ Wv) {
    int sel = blockIdx.y;
    const float* W = (sel == 0) ? Wq : (sel == 1) ? Wk : Wv;
    signed char* WT = (sel == 0) ? g_wtq : (sel == 1) ? g_wtk : g_wtv;
    float* WS = (sel == 0) ? g_wsq : (sel == 1) ? g_wsk : g_wsv;

    int j0 = blockIdx.x * 64;
    int tid = threadIdx.x;
    int tx = tid & 63;
    int ty = tid >> 6;  // 0..3

    float m = 0.0f;
    for (int i = ty; i < D_; i += 4)
        m = fmaxf(m, fabsf(W[i * D_ + j0 + tx]));

    __shared__ float red[4][64];
    __shared__ float sc[64];
    __shared__ signed char tile[64][68];  // [j][m] transposed stage
    red[ty][tx] = m;
    __syncthreads();
    if (ty == 0) {
        float mm = fmaxf(fmaxf(red[0][tx], red[1][tx]), fmaxf(red[2][tx], red[3][tx]));
        sc[tx] = make_scale(mm);
        WS[j0 + tx] = sc[tx];
    }
    __syncthreads();

    for (int kb = 0; kb < D_ / 64; kb++) {
        for (int u = 0; u < 16; u++) {
            int idx = tid + u * 256;
            int mrow = idx >> 6;
            int j = idx & 63;
            float w = W[(kb * 64 + mrow) * D_ + j0 + j];
            tile[j][mrow] = quant_val(w, sc[j]);
        }
        __syncthreads();
        int j = tid >> 2;
        for (int u = 0; u < 4; u++) {
            int mw = (tid & 3) + u * 4;
            unsigned int v = ((unsigned char)tile[j][mw * 4 + 0]) |
                             ((unsigned int)(unsigned char)tile[j][mw * 4 + 1] << 8) |
                             ((unsigned int)(unsigned char)tile[j][mw * 4 + 2] << 16) |
                             ((unsigned int)(unsigned char)tile[j][mw * 4 + 3] << 24);
            ((unsigned int*)WT)[(j0 + j) * (D_ / 4) + kb * 16 + mw] = v;
        }
        __syncthreads();
    }
}

// ---------------- projection GEMM: int8 dp4a, exact int32 accumulate ----------
// grid (D_/64, BT_/64, 3), 256 threads. Output in head layout fp32.
__global__ void proj_gemm_i8_kernel() {
    int z = blockIdx.z;
    const signed char* A = (z == 0) ? g_aq : (z == 1) ? g_ak : g_av;
    const signed char* WT = (z == 0) ? g_wtq : (z == 1) ? g_wtk : g_wtv;
    const float* sA = (z == 0) ? g_sq : (z == 1) ? g_sk : g_sv;
    const float* sW = (z == 0) ? g_wsq : (z == 1) ? g_wsk : g_wsv;
    float* OUT = (z == 0) ? g_q : (z == 1) ? g_kk : g_vv;

    int row0 = blockIdx.y * 64;
    int col0 = blockIdx.x * 64;
    int tid = threadIdx.x;
    int tx = tid & 15;
    int ty = tid >> 4;

    __shared__ int As[64 * 17];
    __shared__ int Bs[64 * 17];

    int acc[4][4];
#pragma unroll
    for (int i = 0; i < 4; i++)
#pragma unroll
        for (int j = 0; j < 4; j++) acc[i][j] = 0;

    const int* Ai = (const int*)A;
    const int* Bi = (const int*)WT;
    int m = tid >> 2;
    int g = tid & 3;

    for (int kb = 0; kb < D_ / 64; kb++) {
        int4 av = *(const int4*)(&Ai[(row0 + m) * (D_ / 4) + kb * 16 + g * 4]);
        int4 bv = *(const int4*)(&Bi[(col0 + m) * (D_ / 4) + kb * 16 + g * 4]);
        As[m * 17 + g * 4 + 0] = av.x;
        As[m * 17 + g * 4 + 1] = av.y;
        As[m * 17 + g * 4 + 2] = av.z;
        As[m * 17 + g * 4 + 3] = av.w;
        Bs[m * 17 + g * 4 + 0] = bv.x;
        Bs[m * 17 + g * 4 + 1] = bv.y;
        Bs[m * 17 + g * 4 + 2] = bv.z;
        Bs[m * 17 + g * 4 + 3] = bv.w;
        __syncthreads();
#pragma unroll
        for (int kk = 0; kk < 16; kk++) {
            int a4[4], b4[4];
#pragma unroll
            for (int i = 0; i < 4; i++) a4[i] = As[(ty * 4 + i) * 17 + kk];
#pragma unroll
            for (int j = 0; j < 4; j++) b4[j] = Bs[(tx * 4 + j) * 17 + kk];
#pragma unroll
            for (int i = 0; i < 4; i++)
#pragma unroll
                for (int j = 0; j < 4; j++) acc[i][j] = __dp4a(a4[i], b4[j], acc[i][j]);
        }
        __syncthreads();
    }

    int h = col0 >> 6;  // 64-col tile == one head
#pragma unroll
    for (int i = 0; i < 4; i++) {
        int r = row0 + ty * 4 + i;
        int b = r >> 11;          // T_ = 2048
        int t = r & (T_ - 1);
        float st = sA[t];
        float4 v;
        v.x = (float)acc[i][0] * (st * sW[col0 + tx * 4 + 0]);
        v.y = (float)acc[i][1] * (st * sW[col0 + tx * 4 + 1]);
        v.z = (float)acc[i][2] * (st * sW[col0 + tx * 4 + 2]);
        v.w = (float)acc[i][3] * (st * sW[col0 + tx * 4 + 3]);
        *(float4*)(&OUT[((b * H_ + h) * T_ + t) * DK_ + tx * 4]) = v;
    }
}

// ---------------- final GEMM: dequant(int8 x) @ Wf (fp32) -> d_out ------------
__global__ void final_gemm_kernel(const float* __restrict__ Wf,
                                  float* __restrict__ out) {
    int row0 = blockIdx.y * 64;
    int col0 = blockIdx.x * 64;
    int tid = threadIdx.x;
    int tx = tid & 15;
    int ty = tid >> 4;

    __shared__ float As[16][68];
    __shared__ float Bs[16][64];

    float acc[4][4];
#pragma unroll
    for (int i = 0; i < 4; i++)
#pragma unroll
        for (int j = 0; j < 4; j++) acc[i][j] = 0.0f;

    int m = tid >> 2;
    int g = tid & 3;
    float sm_scale = g_sx[(row0 + m) & (T_ - 1)];

    for (int kb = 0; kb < D_ / 16; kb++) {
        int av = ((const int*)g_xq8)[(row0 + m) * (D_ / 4) + kb * 4 + g];
#pragma unroll
        for (int u = 0; u < 4; u++) {
            int q8 = (av << (24 - 8 * u)) >> 24;  // sign-extended byte u
            As[g * 4 + u][m] = (float)q8 * sm_scale;
        }
#pragma unroll
        for (int i = 0; i < 4; i++) {
            int idx = tid + i * 256;
            int k = idx >> 6;
            int n = idx & 63;
            Bs[k][n] = Wf[(kb * 16 + k) * D_ + col0 + n];
        }
        __syncthreads();
#pragma unroll
        for (int k = 0; k < 16; k++) {
            float4 a = *(const float4*)(&As[k][ty * 4]);
            float4 b = *(const float4*)(&Bs[k][tx * 4]);
            float avv[4] = {a.x, a.y, a.z, a.w};
            float bvv[4] = {b.x, b.y, b.z, b.w};
#pragma unroll
            for (int i = 0; i < 4; i++)
#pragma unroll
                for (int j = 0; j < 4; j++) acc[i][j] += avv[i] * bvv[j];
        }
        __syncthreads();
    }

#pragma unroll
    for (int i = 0; i < 4; i++) {
        int r = row0 + ty * 4 + i;
        float4 v = make_float4(acc[i][0], acc[i][1], acc[i][2], acc[i][3]);
        *(float4*)(&out[r * D_ + col0 + tx * 4]) = v;
    }
}

// ---------------- single-pass flash attention, conflict-free smem -------------
// BM=BN=64, dk=64, 256 threads, 4x4 per thread.
// Smem: Qs[64][64], Kt[64 d][68 kv] (K transposed; aliased as Ps[64 q][68 kv]),
// Vs[64][64]. K fragments are lane-indexed by COLUMN -> conflict-free.
#define ATT_SMEM ((64 * 64 + 64 * 68 + 64 * 64) * 4)

__global__ void attention_kernel() {
    extern __shared__ float sm[];
    float* Qs = sm;                      // [row][d]   stride 64
    float* Kt = sm + 64 * 64;            // [d][kv]    stride 68 ; aliased as Ps[q][kv]
    float* Vs = sm + 64 * 64 + 64 * 68;  // [kv][d]    stride 64

    int bh = blockIdx.y;
    int q0 = blockIdx.x * 64;
    const float* Q = g_q + bh * T_ * DK_;
    const float* K = g_kk + bh * T_ * DK_;
    const float* V = g_vv + bh * T_ * DK_;

    int tid = threadIdx.x;
    int tx = tid & 15;
    int ty = tid >> 4;

    // load Q tile [row][d]
    for (int idx = tid; idx < 64 * 64; idx += 256) {
        int m = idx >> 6;
        int d = idx & 63;
        Qs[m * 64 + d] = Q[(q0 + m) * DK_ + d];
    }

    float mrow[4], lrow[4], Ov[4][4];
#pragma unroll
    for (int i = 0; i < 4; i++) {
        mrow[i] = -1e30f;
        lrow[i] = 0.0f;
#pragma unroll
        for (int j = 0; j < 4; j++) Ov[i][j] = 0.0f;
    }

    for (int kt = 0; kt < T_ / 64; kt++) {
        __syncthreads();  // prior PV reads of Ps/Vs done; Qs visible on iter 0
        // load K transposed -> Kt[d][kv], V natural -> Vs[kv][d]
#pragma unroll
        for (int u = 0; u < 4; u++) {
            int f = tid + u * 256;   // 0..1023
            int kv = f >> 4;         // 0..63
            int dq = f & 15;         // float4 group in d
            float4 kvv = *(const float4*)(&K[(kt * 64 + kv) * DK_ + dq * 4]);
            Kt[(dq * 4 + 0) * 68 + kv] = kvv.x;
            Kt[(dq * 4 + 1) * 68 + kv] = kvv.y;
            Kt[(dq * 4 + 2) * 68 + kv] = kvv.z;
            Kt[(dq * 4 + 3) * 68 + kv] = kvv.w;
            *(float4*)(&Vs[kv * 64 + dq * 4]) =
                *(const float4*)(&V[(kt * 64 + kv) * DK_ + dq * 4]);
        }
        __syncthreads();

        // S = Q K^T  (q rows ty*4+i, kv cols tx*4+j)
        float s_[4][4];
#pragma unroll
        for (int i = 0; i < 4; i++)
#pragma unroll
            for (int j = 0; j < 4; j++) s_[i][j] = 0.0f;

#pragma unroll 4
        for (int d4 = 0; d4 < 16; d4++) {
            float4 qv[4], kf[4];
#pragma unroll
            for (int i = 0; i < 4; i++)
                qv[i] = *(const float4*)(&Qs[(ty * 4 + i) * 64 + d4 * 4]);
#pragma unroll
            for (int e = 0; e < 4; e++)
                kf[e] = *(const float4*)(&Kt[(d4 * 4 + e) * 68 + tx * 4]);
#pragma unroll
            for (int i = 0; i < 4; i++) {
                s_[i][0] += qv[i].x * kf[0].x;
                s_[i][1] += qv[i].x * kf[0].y;
                s_[i][2] += qv[i].x * kf[0].z;
                s_[i][3] += qv[i].x * kf[0].w;
                s_[i][0] += qv[i].y * kf[1].x;
                s_[i][1] += qv[i].y * kf[1].y;
                s_[i][2] += qv[i].y * kf[1].z;
                s_[i][3] += qv[i].y * kf[1].w;
                s_[i][0] += qv[i].z * kf[2].x;
                s_[i][1] += qv[i].z * kf[2].y;
                s_[i][2] += qv[i].z * kf[2].z;
                s_[i][3] += qv[i].z * kf[2].w;
                s_[i][0] += qv[i].w * kf[3].x;
                s_[i][1] += qv[i].w * kf[3].y;
                s_[i][2] += qv[i].w * kf[3].z;
                s_[i][3] += qv[i].w * kf[3].w;
            }
        }
        __syncthreads();  // all Kt reads done; safe to overwrite with Ps

        // online softmax update + P tile store
#pragma unroll
        for (int i = 0; i < 4; i++) {
            float sv[4];
            float tm = -1e30f;
#pragma unroll
            for (int j = 0; j < 4; j++) {
                sv[j] = div_full(s_[i][j], 8.0f);   // scores / sqrt(dk)
                tm = fmaxf(tm, sv[j]);
            }
#pragma unroll
            for (int off = 8; off > 0; off >>= 1)
                tm = fmaxf(tm, __shfl_xor_sync(0xFFFFFFFFu, tm, off, 16));
            float newm = fmaxf(mrow[i], tm);
            float alpha = __expf(mrow[i] - newm);
            float p[4];
            float rs = 0.0f;
#pragma unroll
            for (int j = 0; j < 4; j++) {
                p[j] = __expf(sv[j] - newm);
                rs += p[j];
            }
#pragma unroll
            for (int off = 8; off > 0; off >>= 1)
                rs += __shfl_xor_sync(0xFFFFFFFFu, rs, off, 16);
            lrow[i] = lrow[i] * alpha + rs;
            mrow[i] = newm;
#pragma unroll
            for (int j = 0; j < 4; j++) Ov[i][j] *= alpha;
            *(float4*)(&Kt[(ty * 4 + i) * 68 + tx * 4]) =
                make_float4(p[0], p[1], p[2], p[3]);
        }
        __syncthreads();

        // O += P V  (k-dim = kv; P broadcast by row, V lane-indexed by column)
#pragma unroll 4
        for (int j4 = 0; j4 < 16; j4++) {
            float4 pv[4], vr[4];
#pragma unroll
            for (int i = 0; i < 4; i++)
                pv[i] = *(const float4*)(&Kt[(ty * 4 + i) * 68 + j4 * 4]);
#pragma unroll
            for (int e = 0; e < 4; e++)
                vr[e] = *(const float4*)(&Vs[(j4 * 4 + e) * 64 + tx * 4]);
#pragma unroll
            for (int i = 0; i < 4; i++) {
                Ov[i][0] += pv[i].x * vr[0].x;
                Ov[i][1] += pv[i].x * vr[0].y;
                Ov[i][2] += pv[i].x * vr[0].z;
                Ov[i][3] += pv[i].x * vr[0].w;
                Ov[i][0] += pv[i].y * vr[1].x;
                Ov[i][1] += pv[i].y * vr[1].y;
                Ov[i][2] += pv[i].y * vr[1].z;
                Ov[i][3] += pv[i].y * vr[1].w;
                Ov[i][0] += pv[i].z * vr[2].x;
                Ov[i][1] += pv[i].z * vr[2].y;
                Ov[i][2] += pv[i].z * vr[2].z;
                Ov[i][3] += pv[i].z * vr[2].w;
                Ov[i][0] += pv[i].w * vr[3].x;
                Ov[i][1] += pv[i].w * vr[3].y;
                Ov[i][2] += pv[i].w * vr[3].z;
                Ov[i][3] += pv[i].w * vr[3].w;
            }
        }
    }

    int b = bh >> 3;   // H_ = 8
    int h = bh & 7;
#pragma unroll
    for (int i = 0; i < 4; i++) {
        int t = q0 + ty * 4 + i;
        float4 v;
        v.x = div_full(Ov[i][0], lrow[i]);
        v.y = div_full(Ov[i][1], lrow[i]);
        v.z = div_full(Ov[i][2], lrow[i]);
        v.w = div_full(Ov[i][3], lrow[i]);
        *(float4*)(&g_x[(b * T_ + t) * D_ + h * DK_ + tx * 4]) = v;
    }
}

// ------------------------------ launcher --------------------------------------
extern "C" void kernel_launch(void* const* d_in, const int* in_sizes, int n_in,
                              void* d_out, int out_size) {
    (void)in_sizes; (void)n_in; (void)out_size;
    const float* q  = (const float*)d_in[0];
    const float* k  = (const float*)d_in[1];
    const float* v  = (const float*)d_in[2];
    const float* Wq = (const float*)d_in[3];
    const float* Wk = (const float*)d_in[4];
    const float* Wv = (const float*)d_in[5];
    const float* Wf = (const float*)d_in[6];
    float* out = (float*)d_out;

    cudaFuncSetAttribute(attention_kernel,
                         cudaFuncAttributeMaxDynamicSharedMemorySize, ATT_SMEM);

    act_quant_kernel<<<dim3(T_, 3), 256>>>(q, k, v, 0);
    weight_quant_kernel<<<dim3(D_ / 64, 3), 256>>>(Wq, Wk, Wv);
    proj_gemm_i8_kernel<<<dim3(D_ / 64, BT_ / 64, 3), 256>>>();
    attention_kernel<<<dim3(T_ / 64, B_ * H_), 256, ATT_SMEM>>>();
    act_quant_kernel<<<dim3(T_, 1), 256>>>(q, k, v, 1);
    final_gemm_kernel<<<dim3(D_ / 64, BT_ / 64), 256>>>(Wf, out);
}

// round 7
// speedup vs baseline: 2.6142x; 1.1593x over previous
#include <cuda_runtime.h>
#include <math.h>

// Problem constants
#define B_  4
#define T_  2048
#define D_  512
#define H_  8
#define DK_ 64
#define BT_ (B_ * T_)

// ---------------- device scratch (no allocations allowed) ----------------
__device__ float g_sq[T_], g_sk[T_], g_sv[T_], g_sx[T_];       // per-token act scales
__device__ float g_wsq[D_], g_wsk[D_], g_wsv[D_];              // per-col weight scales
__device__ signed char g_aq[BT_ * D_], g_ak[BT_ * D_], g_av[BT_ * D_]; // int8 acts
__device__ signed char g_xq8[BT_ * D_];                         // int8 of attention out
__device__ signed char g_wtq[D_ * D_], g_wtk[D_ * D_], g_wtv[D_ * D_]; // int8 W^T [j][k]
__device__ float g_q[B_ * H_ * T_ * DK_];
__device__ float g_kk[B_ * H_ * T_ * DK_];
__device__ float g_kkT[B_ * H_ * DK_ * T_];   // K transposed: [bh][d][t]
__device__ float g_vv[B_ * H_ * T_ * DK_];
__device__ float g_x[BT_ * D_];

// ---- emulate XLA:GPU's f32 division (div.full.f32, <=2ulp, not IEEE) ----
__device__ __forceinline__ float div_full(float a, float b) {
    float r;
    asm("div.full.f32 %0, %1, %2;" : "=f"(r) : "f"(a), "f"(b));
    return r;
}
__device__ __forceinline__ float make_scale(float absmax) {
    return fmaxf(div_full(absmax, 127.0f), 1e-8f);
}
__device__ __forceinline__ signed char quant_val(float v, float s) {
    float q = rintf(div_full(v, s));
    q = fminf(127.0f, fmaxf(-128.0f, q));
    return (signed char)(int)q;
}

// ---- packed f32x2 helpers (Blackwell) — each lane an independent fp32 acc ----
typedef unsigned long long ull;
__device__ __forceinline__ ull fma2(ull a, ull b, ull c) {
    ull d;
    asm("fma.rn.f32x2 %0, %1, %2, %3;" : "=l"(d) : "l"(a), "l"(b), "l"(c));
    return d;
}
__device__ __forceinline__ ull mul2(ull a, ull b) {
    ull d;
    asm("mul.rn.f32x2 %0, %1, %2;" : "=l"(d) : "l"(a), "l"(b));
    return d;
}
__device__ __forceinline__ ull dup2(float x) {
    ull d;
    asm("mov.b64 %0, {%1, %1};" : "=l"(d) : "f"(x));
    return d;
}
__device__ __forceinline__ float2 unpk(ull v) {
    float lo, hi;
    asm("mov.b64 {%0, %1}, %2;" : "=f"(lo), "=f"(hi) : "l"(v));
    return make_float2(lo, hi);
}

// ---------------- per-token activation scale + int8 quantize ------------------
__global__ void act_quant_kernel(const float* __restrict__ xq,
                                 const float* __restrict__ xk,
                                 const float* __restrict__ xv,
                                 int final_mode) {
    int t = blockIdx.x;
    const float* x;
    float* sptr;
    signed char* outq;
    if (final_mode) {
        x = g_x; sptr = g_sx; outq = g_xq8;
    } else {
        int sel = blockIdx.y;
        x = (sel == 0) ? xq : (sel == 1) ? xk : xv;
        sptr = (sel == 0) ? g_sq : (sel == 1) ? g_sk : g_sv;
        outq = (sel == 0) ? g_aq : (sel == 1) ? g_ak : g_av;
    }
    int tid = threadIdx.x;
    float m = 0.0f;
    for (int idx = tid; idx < B_ * D_; idx += 256) {
        int b = idx >> 9;          // D_ = 512
        int d = idx & (D_ - 1);
        m = fmaxf(m, fabsf(x[(b * T_ + t) * D_ + d]));
    }
    __shared__ float red[256];
    __shared__ float s_sh;
    red[tid] = m;
    __syncthreads();
    for (int s2 = 128; s2 > 0; s2 >>= 1) {
        if (tid < s2) red[tid] = fmaxf(red[tid], red[tid + s2]);
        __syncthreads();
    }
    if (tid == 0) { s_sh = make_scale(red[0]); sptr[t] = s_sh; }
    __syncthreads();
    float s = s_sh;
    for (int idx = tid; idx < B_ * D_; idx += 256) {
        int b = idx >> 9;
        int d = idx & (D_ - 1);
        int off = (b * T_ + t) * D_ + d;
        outq[off] = quant_val(x[off], s);
    }
}

// ---------------- weight quant: per-col scale, store int8 W^T -----------------
__global__ void weight_quant_kernel(const float* __restrict__ Wq,
                                    const float* __restrict__ Wk,
                                    const float* __restrict__ Wv) {
    int sel = blockIdx.y;
    const float* W = (sel == 0) ? Wq : (sel == 1) ? Wk : Wv;
    signed char* WT = (sel == 0) ? g_wtq : (sel == 1) ? g_wtk : g_wtv;
    float* WS = (sel == 0) ? g_wsq : (sel == 1) ? g_wsk : g_wsv;

    int j0 = blockIdx.x * 64;
    int tid = threadIdx.x;
    int tx = tid & 63;
    int ty = tid >> 6;  // 0..3

    float m = 0.0f;
    for (int i = ty; i < D_; i += 4)
        m = fmaxf(m, fabsf(W[i * D_ + j0 + tx]));

    __shared__ float red[4][64];
    __shared__ float sc[64];
    __shared__ signed char tile[64][68];  // [j][m] transposed stage
    red[ty][tx] = m;
    __syncthreads();
    if (ty == 0) {
        float mm = fmaxf(fmaxf(red[0][tx], red[1][tx]), fmaxf(red[2][tx], red[3][tx]));
        sc[tx] = make_scale(mm);
        WS[j0 + tx] = sc[tx];
    }
    __syncthreads();

    for (int kb = 0; kb < D_ / 64; kb++) {
        for (int u = 0; u < 16; u++) {
            int idx = tid + u * 256;
            int mrow = idx >> 6;
            int j = idx & 63;
            float w = W[(kb * 64 + mrow) * D_ + j0 + j];
            tile[j][mrow] = quant_val(w, sc[j]);
        }
        __syncthreads();
        int j = tid >> 2;
        for (int u = 0; u < 4; u++) {
            int mw = (tid & 3) + u * 4;
            unsigned int v = ((unsigned char)tile[j][mw * 4 + 0]) |
                             ((unsigned int)(unsigned char)tile[j][mw * 4 + 1] << 8) |
                             ((unsigned int)(unsigned char)tile[j][mw * 4 + 2] << 16) |
                             ((unsigned int)(unsigned char)tile[j][mw * 4 + 3] << 24);
            ((unsigned int*)WT)[(j0 + j) * (D_ / 4) + kb * 16 + mw] = v;
        }
        __syncthreads();
    }
}

// ---------------- projection GEMM: int8 dp4a, exact int32 accumulate ----------
__global__ void proj_gemm_i8_kernel() {
    int z = blockIdx.z;
    const signed char* A = (z == 0) ? g_aq : (z == 1) ? g_ak : g_av;
    const signed char* WT = (z == 0) ? g_wtq : (z == 1) ? g_wtk : g_wtv;
    const float* sA = (z == 0) ? g_sq : (z == 1) ? g_sk : g_sv;
    const float* sW = (z == 0) ? g_wsq : (z == 1) ? g_wsk : g_wsv;
    float* OUT = (z == 0) ? g_q : (z == 1) ? g_kk : g_vv;

    int row0 = blockIdx.y * 64;
    int col0 = blockIdx.x * 64;
    int tid = threadIdx.x;
    int tx = tid & 15;
    int ty = tid >> 4;

    __shared__ int As[64 * 17];
    __shared__ int Bs[64 * 17];

    int acc[4][4];
#pragma unroll
    for (int i = 0; i < 4; i++)
#pragma unroll
        for (int j = 0; j < 4; j++) acc[i][j] = 0;

    const int* Ai = (const int*)A;
    const int* Bi = (const int*)WT;
    int m = tid >> 2;
    int g = tid & 3;

    for (int kb = 0; kb < D_ / 64; kb++) {
        int4 av = *(const int4*)(&Ai[(row0 + m) * (D_ / 4) + kb * 16 + g * 4]);
        int4 bv = *(const int4*)(&Bi[(col0 + m) * (D_ / 4) + kb * 16 + g * 4]);
        As[m * 17 + g * 4 + 0] = av.x;
        As[m * 17 + g * 4 + 1] = av.y;
        As[m * 17 + g * 4 + 2] = av.z;
        As[m * 17 + g * 4 + 3] = av.w;
        Bs[m * 17 + g * 4 + 0] = bv.x;
        Bs[m * 17 + g * 4 + 1] = bv.y;
        Bs[m * 17 + g * 4 + 2] = bv.z;
        Bs[m * 17 + g * 4 + 3] = bv.w;
        __syncthreads();
#pragma unroll
        for (int kk = 0; kk < 16; kk++) {
            int a4[4], b4[4];
#pragma unroll
            for (int i = 0; i < 4; i++) a4[i] = As[(ty * 4 + i) * 17 + kk];
#pragma unroll
            for (int j = 0; j < 4; j++) b4[j] = Bs[(tx * 4 + j) * 17 + kk];
#pragma unroll
            for (int i = 0; i < 4; i++)
#pragma unroll
                for (int j = 0; j < 4; j++) acc[i][j] = __dp4a(a4[i], b4[j], acc[i][j]);
        }
        __syncthreads();
    }

    int h = col0 >> 6;  // 64-col tile == one head
#pragma unroll
    for (int i = 0; i < 4; i++) {
        int r = row0 + ty * 4 + i;
        int b = r >> 11;          // T_ = 2048
        int t = r & (T_ - 1);
        float st = sA[t];
        float4 v;
        v.x = (float)acc[i][0] * (st * sW[col0 + tx * 4 + 0]);
        v.y = (float)acc[i][1] * (st * sW[col0 + tx * 4 + 1]);
        v.z = (float)acc[i][2] * (st * sW[col0 + tx * 4 + 2]);
        v.w = (float)acc[i][3] * (st * sW[col0 + tx * 4 + 3]);
        *(float4*)(&OUT[((b * H_ + h) * T_ + t) * DK_ + tx * 4]) = v;
    }
}

// ---------------- K transpose: g_kk [bh][t][d] -> g_kkT [bh][d][t] ------------
// grid (T_/64, B_*H_), 256 threads. Xor-swizzled smem tile, coalesced both sides.
__global__ void transpose_k_kernel() {
    __shared__ float tile[64 * 68];
    int bh = blockIdx.y;
    int t0 = blockIdx.x * 64;
    const float* K = g_kk + bh * T_ * DK_;
    int tid = threadIdx.x;
#pragma unroll
    for (int u = 0; u < 4; u++) {
        int f = tid + u * 256;
        int tt = f >> 4;       // 0..63 token row
        int dq = f & 15;       // float4 group in d
        float4 v = *(const float4*)(&K[(t0 + tt) * DK_ + dq * 4]);
        int pc = dq ^ (tt & 15);   // xor swizzle on 16B columns
        *(float4*)(&tile[tt * 68 + pc * 4]) = v;
    }
    __syncthreads();
#pragma unroll
    for (int u = 0; u < 4; u++) {
        int f = tid + u * 256;
        int d = f >> 4;        // 0..63 dim row
        int tq = f & 15;       // float4 group in t
        float4 v;
#pragma unroll
        for (int e = 0; e < 4; e++) {
            int row = tq * 4 + e;
            int pc = (d >> 2) ^ (row & 15);
            ((float*)&v)[e] = tile[row * 68 + pc * 4 + (d & 3)];
        }
        *(float4*)(&g_kkT[(bh * DK_ + d) * T_ + t0 + tq * 4]) = v;
    }
}

// ---------------- single-pass flash attention: FFMA2, 8x4 tiles ---------------
// BM=BN=64, dk=64, 128 threads, thread tile 8 rows x 4 cols.
// tx = tid&15 (cols tx*4), ty = tid>>4 (0..7, rows ty*8+i).
// Smem: Qs[64][64], PK[64][68] (Kt[d][kv] aliased w/ P[q][kv]), Vs[64][64].
#define ATT_SMEM ((64 * 64 + 64 * 68 + 64 * 64) * 4)

__global__ void __launch_bounds__(128, 4) attention_kernel() {
    extern __shared__ float sm[];
    float* Qs = sm;                      // [row][d]   stride 64
    float* PK = sm + 64 * 64;            // Kt[d][kv] / Ps[q][kv], stride 68
    float* Vs = sm + 64 * 64 + 64 * 68;  // [kv][d]    stride 64

    int bh = blockIdx.y;
    int q0 = blockIdx.x * 64;
    const float* Q = g_q + bh * T_ * DK_;
    const float* KT = g_kkT + bh * DK_ * T_;
    const float* V = g_vv + bh * T_ * DK_;

    int tid = threadIdx.x;
    int tx = tid & 15;
    int ty = tid >> 4;

    // load Q tile [row][d]
#pragma unroll
    for (int u = 0; u < 8; u++) {
        int f = tid + u * 128;
        int m = f >> 4;
        int dq = f & 15;
        *(float4*)(&Qs[m * 64 + dq * 4]) =
            *(const float4*)(&Q[(q0 + m) * DK_ + dq * 4]);
    }

    float mrow[8], lrow[8];
    ull Ov2[8][2];
#pragma unroll
    for (int i = 0; i < 8; i++) {
        mrow[i] = -1e30f;
        lrow[i] = 0.0f;
        Ov2[i][0] = 0ull;
        Ov2[i][1] = 0ull;
    }

    for (int kt = 0; kt < T_ / 64; kt++) {
        __syncthreads();  // prior P/V reads done; Qs visible on iter 0
        // Kt tile from g_kkT (already transposed): rows d, cols kv. And V natural.
#pragma unroll
        for (int u = 0; u < 8; u++) {
            int f = tid + u * 128;
            int r = f >> 4;          // d for Kt / kv for Vs
            int c = f & 15;          // float4 group
            *(float4*)(&PK[r * 68 + c * 4]) =
                *(const float4*)(&KT[r * T_ + kt * 64 + c * 4]);
            *(float4*)(&Vs[r * 64 + c * 4]) =
                *(const float4*)(&V[(kt * 64 + r) * DK_ + c * 4]);
        }
        __syncthreads();

        // S = Q K^T : s2[i] = two f32x2 pairs over cols (tx*4 .. tx*4+3)
        ull s2[8][2];
#pragma unroll
        for (int i = 0; i < 8; i++) { s2[i][0] = 0ull; s2[i][1] = 0ull; }

#pragma unroll 2
        for (int d4 = 0; d4 < 16; d4++) {
            ulonglong2 kf0 = *(const ulonglong2*)(&PK[(d4 * 4 + 0) * 68 + tx * 4]);
            ulonglong2 kf1 = *(const ulonglong2*)(&PK[(d4 * 4 + 1) * 68 + tx * 4]);
            ulonglong2 kf2 = *(const ulonglong2*)(&PK[(d4 * 4 + 2) * 68 + tx * 4]);
            ulonglong2 kf3 = *(const ulonglong2*)(&PK[(d4 * 4 + 3) * 68 + tx * 4]);
#pragma unroll
            for (int i = 0; i < 8; i++) {
                float4 qv = *(const float4*)(&Qs[(ty * 8 + i) * 64 + d4 * 4]);
                ull ax = dup2(qv.x), ay = dup2(qv.y), az = dup2(qv.z), aw = dup2(qv.w);
                s2[i][0] = fma2(ax, kf0.x, s2[i][0]);
                s2[i][1] = fma2(ax, kf0.y, s2[i][1]);
                s2[i][0] = fma2(ay, kf1.x, s2[i][0]);
                s2[i][1] = fma2(ay, kf1.y, s2[i][1]);
                s2[i][0] = fma2(az, kf2.x, s2[i][0]);
                s2[i][1] = fma2(az, kf2.y, s2[i][1]);
                s2[i][0] = fma2(aw, kf3.x, s2[i][0]);
                s2[i][1] = fma2(aw, kf3.y, s2[i][1]);
            }
        }
        __syncthreads();  // all Kt reads done; safe to overwrite with Ps

        // online softmax update + P tile store
#pragma unroll
        for (int i = 0; i < 8; i++) {
            float2 lo = unpk(s2[i][0]);
            float2 hi = unpk(s2[i][1]);
            float sv0 = div_full(lo.x, 8.0f);
            float sv1 = div_full(lo.y, 8.0f);
            float sv2 = div_full(hi.x, 8.0f);
            float sv3 = div_full(hi.y, 8.0f);
            float tm = fmaxf(fmaxf(sv0, sv1), fmaxf(sv2, sv3));
#pragma unroll
            for (int off = 8; off > 0; off >>= 1)
                tm = fmaxf(tm, __shfl_xor_sync(0xFFFFFFFFu, tm, off, 16));
            float newm = fmaxf(mrow[i], tm);
            float alpha = __expf(mrow[i] - newm);
            float p0 = __expf(sv0 - newm);
            float p1 = __expf(sv1 - newm);
            float p2 = __expf(sv2 - newm);
            float p3 = __expf(sv3 - newm);
            float rs = 0.0f;
            rs += p0; rs += p1; rs += p2; rs += p3;
#pragma unroll
            for (int off = 8; off > 0; off >>= 1)
                rs += __shfl_xor_sync(0xFFFFFFFFu, rs, off, 16);
            lrow[i] = lrow[i] * alpha + rs;
            mrow[i] = newm;
            ull am = dup2(alpha);
            Ov2[i][0] = mul2(Ov2[i][0], am);
            Ov2[i][1] = mul2(Ov2[i][1], am);
            *(float4*)(&PK[(ty * 8 + i) * 68 + tx * 4]) =
                make_float4(p0, p1, p2, p3);
        }
        __syncthreads();

        // O += P V : Ov2[i] = two f32x2 pairs over d (tx*4 .. tx*4+3)
#pragma unroll 2
        for (int j4 = 0; j4 < 16; j4++) {
            ulonglong2 vr0 = *(const ulonglong2*)(&Vs[(j4 * 4 + 0) * 64 + tx * 4]);
            ulonglong2 vr1 = *(const ulonglong2*)(&Vs[(j4 * 4 + 1) * 64 + tx * 4]);
            ulonglong2 vr2 = *(const ulonglong2*)(&Vs[(j4 * 4 + 2) * 64 + tx * 4]);
            ulonglong2 vr3 = *(const ulonglong2*)(&Vs[(j4 * 4 + 3) * 64 + tx * 4]);
#pragma unroll
            for (int i = 0; i < 8; i++) {
                float4 pv = *(const float4*)(&PK[(ty * 8 + i) * 68 + j4 * 4]);
                ull ax = dup2(pv.x), ay = dup2(pv.y), az = dup2(pv.z), aw = dup2(pv.w);
                Ov2[i][0] = fma2(ax, vr0.x, Ov2[i][0]);
                Ov2[i][1] = fma2(ax, vr0.y, Ov2[i][1]);
                Ov2[i][0] = fma2(ay, vr1.x, Ov2[i][0]);
                Ov2[i][1] = fma2(ay, vr1.y, Ov2[i][1]);
                Ov2[i][0] = fma2(az, vr2.x, Ov2[i][0]);
                Ov2[i][1] = fma2(az, vr2.y, Ov2[i][1]);
                Ov2[i][0] = fma2(aw, vr3.x, Ov2[i][0]);
                Ov2[i][1] = fma2(aw, vr3.y, Ov2[i][1]);
            }
        }
    }

    int b = bh >> 3;   // H_ = 8
    int h = bh & 7;
#pragma unroll
    for (int i = 0; i < 8; i++) {
        int t = q0 + ty * 8 + i;
        float2 o01 = unpk(Ov2[i][0]);
        float2 o23 = unpk(Ov2[i][1]);
        float4 v;
        v.x = div_full(o01.x, lrow[i]);
        v.y = div_full(o01.y, lrow[i]);
        v.z = div_full(o23.x, lrow[i]);
        v.w = div_full(o23.y, lrow[i]);
        *(float4*)(&g_x[(b * T_ + t) * D_ + h * DK_ + tx * 4]) = v;
    }
}

// ---------------- final GEMM: dequant(int8 x) @ Wf (fp32) -> d_out ------------
__global__ void final_gemm_kernel(const float* __restrict__ Wf,
                                  float* __restrict__ out) {
    int row0 = blockIdx.y * 64;
    int col0 = blockIdx.x * 64;
    int tid = threadIdx.x;
    int tx = tid & 15;
    int ty = tid >> 4;

    __shared__ float As[16][68];
    __shared__ float Bs[16][64];

    float acc[4][4];
#pragma unroll
    for (int i = 0; i < 4; i++)
#pragma unroll
        for (int j = 0; j < 4; j++) acc[i][j] = 0.0f;

    int m = tid >> 2;
    int g = tid & 3;
    float sm_scale = g_sx[(row0 + m) & (T_ - 1)];

    for (int kb = 0; kb < D_ / 16; kb++) {
        int av = ((const int*)g_xq8)[(row0 + m) * (D_ / 4) + kb * 4 + g];
#pragma unroll
        for (int u = 0; u < 4; u++) {
            int q8 = (av << (24 - 8 * u)) >> 24;  // sign-extended byte u
            As[g * 4 + u][m] = (float)q8 * sm_scale;
        }
#pragma unroll
        for (int i = 0; i < 4; i++) {
            int idx = tid + i * 256;
            int k = idx >> 6;
            int n = idx & 63;
            Bs[k][n] = Wf[(kb * 16 + k) * D_ + col0 + n];
        }
        __syncthreads();
#pragma unroll
        for (int k = 0; k < 16; k++) {
            float4 a = *(const float4*)(&As[k][ty * 4]);
            float4 b = *(const float4*)(&Bs[k][tx * 4]);
            float avv[4] = {a.x, a.y, a.z, a.w};
            float bvv[4] = {b.x, b.y, b.z, b.w};
#pragma unroll
            for (int i = 0; i < 4; i++)
#pragma unroll
                for (int j = 0; j < 4; j++) acc[i][j] += avv[i] * bvv[j];
        }
        __syncthreads();
    }

#pragma unroll
    for (int i = 0; i < 4; i++) {
        int r = row0 + ty * 4 + i;
        float4 v = make_float4(acc[i][0], acc[i][1], acc[i][2], acc[i][3]);
        *(float4*)(&out[r * D_ + col0 + tx * 4]) = v;
    }
}

// ------------------------------ launcher --------------------------------------
extern "C" void kernel_launch(void* const* d_in, const int* in_sizes, int n_in,
                              void* d_out, int out_size) {
    (void)in_sizes; (void)n_in; (void)out_size;
    const float* q  = (const float*)d_in[0];
    const float* k  = (const float*)d_in[1];
    const float* v  = (const float*)d_in[2];
    const float* Wq = (const float*)d_in[3];
    const float* Wk = (const float*)d_in[4];
    const float* Wv = (const float*)d_in[5];
    const float* Wf = (const float*)d_in[6];
    float* out = (float*)d_out;

    cudaFuncSetAttribute(attention_kernel,
                         cudaFuncAttributeMaxDynamicSharedMemorySize, ATT_SMEM);

    act_quant_kernel<<<dim3(T_, 3), 256>>>(q, k, v, 0);
    weight_quant_kernel<<<dim3(D_ / 64, 3), 256>>>(Wq, Wk, Wv);
    proj_gemm_i8_kernel<<<dim3(D_ / 64, BT_ / 64, 3), 256>>>();
    transpose_k_kernel<<<dim3(T_ / 64, B_ * H_), 256>>>();
    attention_kernel<<<dim3(T_ / 64, B_ * H_), 128, ATT_SMEM>>>();
    act_quant_kernel<<<dim3(T_, 1), 256>>>(q, k, v, 1);
    final_gemm_kernel<<<dim3(D_ / 64, BT_ / 64), 256>>>(Wf, out);
}